// round 10
// baseline (speedup 1.0000x reference)
#include <cuda_runtime.h>
#include <math_constants.h>

#define B     4
#define CIN   3
#define NPTS  8192
#define COUT  64
#define KMAX  40
#define K0    10
#define K1    20
#define BN_EPS 1e-5f
#define FULL  0xFFFFFFFFu
#define WPB   8          // warps per block (topk)
#define QPW   4          // queries per warp
#define CAP   192        // candidate buffer capacity per query
#define EPTS  4          // points per block (edgeconv)

// packed points: (x, y, z, -0.5*||p||^2)
__device__ float4 g_pts[B * NPTS];
// gathered neighbor coords per (b,n): 40 float4, sorted by descending dist
__device__ float4 g_nb[(size_t)B * NPTS * KMAX];

// monotone float<->uint transforms (order-preserving over all finite floats)
__device__ __forceinline__ unsigned ordf(float f) {
    unsigned u = __float_as_uint(f);
    return u ^ (unsigned)(((int)u >> 31) | 0x80000000);
}
__device__ __forceinline__ float unordf(unsigned o) {
    unsigned u = (o & 0x80000000u) ? (o ^ 0x80000000u) : ~o;
    return __uint_as_float(u);
}

__device__ __forceinline__ unsigned long long u64mn(unsigned long long a, unsigned long long b) { return a < b ? a : b; }
__device__ __forceinline__ unsigned long long u64mx(unsigned long long a, unsigned long long b) { return a > b ? a : b; }
__device__ __forceinline__ unsigned u32mn(unsigned a, unsigned b) { return a < b ? a : b; }
__device__ __forceinline__ unsigned u32mx(unsigned a, unsigned b) { return a > b ? a : b; }

// ascending bitonic sort of 64 u32 keys, 2 per lane (slot lane, slot lane+32)
__device__ __forceinline__ void bitonic64_u32(unsigned &k0, unsigned &k1, int lane) {
#pragma unroll
    for (int k = 2; k <= 64; k <<= 1) {
#pragma unroll
        for (int s = 32; s > 0; s >>= 1) {
            if (s >= k) continue;
            if (s == 32) {
                unsigned lo = u32mn(k0, k1), hi = u32mx(k0, k1);
                k0 = lo; k1 = hi;
            } else {
                unsigned p0 = __shfl_xor_sync(FULL, k0, s);
                unsigned p1 = __shfl_xor_sync(FULL, k1, s);
                bool low = (lane & s) == 0;
                bool d0 = (lane & k) == 0;
                bool d1 = ((lane + 32) & k) == 0;
                k0 = (low == d0) ? u32mn(k0, p0) : u32mx(k0, p0);
                k1 = (low == d1) ? u32mn(k1, p1) : u32mx(k1, p1);
            }
        }
    }
}

// ascending bitonic sort of 64 u64 keys, 2 per lane
__device__ __forceinline__ void bitonic64_u64(unsigned long long &k0,
                                              unsigned long long &k1, int lane) {
#pragma unroll
    for (int k = 2; k <= 64; k <<= 1) {
#pragma unroll
        for (int s = 32; s > 0; s >>= 1) {
            if (s >= k) continue;
            if (s == 32) {
                unsigned long long lo = u64mn(k0, k1), hi = u64mx(k0, k1);
                k0 = lo; k1 = hi;
            } else {
                unsigned long long p0 = __shfl_xor_sync(FULL, k0, s);
                unsigned long long p1 = __shfl_xor_sync(FULL, k1, s);
                bool low = (lane & s) == 0;
                bool d0 = (lane & k) == 0;
                bool d1 = ((lane + 32) & k) == 0;
                k0 = (low == d0) ? u64mn(k0, p0) : u64mx(k0, p0);
                k1 = (low == d1) ? u64mn(k1, p1) : u64mx(k1, p1);
            }
        }
    }
}

// merge sorted-asc (k0,k1) with sorted-asc (s0,s1): keep smallest 64, sorted asc
__device__ __forceinline__ void merge64(unsigned long long &k0, unsigned long long &k1,
                                        unsigned long long s0, unsigned long long s1,
                                        int lane) {
    unsigned long long r0 = __shfl_sync(FULL, s1, 31 - lane);
    unsigned long long r1 = __shfl_sync(FULL, s0, 31 - lane);
    k0 = u64mn(k0, r0);
    k1 = u64mn(k1, r1);
    unsigned long long lo = u64mn(k0, k1), hi = u64mx(k0, k1);
    k0 = lo; k1 = hi;
#pragma unroll
    for (int s = 16; s > 0; s >>= 1) {
        unsigned long long p0 = __shfl_xor_sync(FULL, k0, s);
        unsigned long long p1 = __shfl_xor_sync(FULL, k1, s);
        bool low = (lane & s) == 0;
        k0 = low ? u64mn(k0, p0) : u64mx(k0, p0);
        k1 = low ? u64mn(k1, p1) : u64mx(k1, p1);
    }
}

// ---------------------------------------------------------------------------
// Phase 0: pack planar [B,3,N] into float4 (x,y,z, -0.5*|p|^2)
// ---------------------------------------------------------------------------
__global__ void pack_kernel(const float* __restrict__ x) {
    int i = blockIdx.x * blockDim.x + threadIdx.x;   // 0 .. B*NPTS-1
    int b = i >> 13;
    int m = i & (NPTS - 1);
    const float* xb = x + (size_t)b * CIN * NPTS;
    float px = xb[m];
    float py = xb[NPTS + m];
    float pz = xb[2 * NPTS + m];
    float t = px * px;
    t = fmaf(py, py, t);
    t = fmaf(pz, pz, t);
    g_pts[i] = make_float4(px, py, pz, -0.5f * t);
}

// ---------------------------------------------------------------------------
// Phase 1: two-pass exact top-40, 4 queries per warp, candidates via L1.
// Ranking uses w(p) = <q,p> - 0.5|p|^2, a strictly monotone per-query
// transform of -|q-p|^2: identical neighbor ordering.
// Pass 1 (HALF-SAMPLE): per-lane top-2 over the even 32-blocks (4096 pts)
//         -> bitonic64 -> 40th of the kept 64 sample elements = threshold.
//         The 40th-largest of ANY stream subset <= true 40th-largest, so
//         the threshold is deterministically conservative; final selection
//         is unchanged (exactness lives entirely in pass 2 + sort).
// Pass 2: collect INDICES of all candidates with w >= thr (captures every
//         top-40 member incl. boundary ties); E[count]~80, CAP=192 (~12σ).
// Epilogue: recompute w for survivors (identical expression => bit-equal),
//         sort keys (~ord(w)<<13 | idx) == (w desc, idx asc) == lax.top_k
//         order; gather neighbor float4s to g_nb.
// ---------------------------------------------------------------------------
__global__ void __launch_bounds__(32 * WPB, 4) topk_kernel() {
    __shared__ unsigned bufall[WPB * QPW * CAP];   // 24 KB

    const int lane = threadIdx.x & 31;
    const int warp = threadIdx.x >> 5;
    const int q0 = (blockIdx.x * WPB + warp) * QPW;   // b*NPTS + n
    const int b = q0 >> 13;                           // block stays in one batch
    const float4* __restrict__ bp = g_pts + b * NPTS;
    unsigned* buf = bufall + (size_t)warp * QPW * CAP;

    float qx[QPW], qy[QPW], qz[QPW];
#pragma unroll
    for (int q = 0; q < QPW; q++) {
        float4 Q = __ldg(&g_pts[q0 + q]);
        qx[q] = Q.x; qy[q] = Q.y; qz[q] = Q.z;
    }

    // ---- pass 1: per-lane top-2 over half-sample (even 32-blocks) ----
    float t1[QPW], t2[QPW];
#pragma unroll
    for (int q = 0; q < QPW; q++) { t1[q] = -CUDART_INF_F; t2[q] = -CUDART_INF_F; }

#pragma unroll 4
    for (int it = 0; it < NPTS; it += 64) {
        float4 p = __ldg(bp + it + lane);
#pragma unroll
        for (int q = 0; q < QPW; q++) {
            float v = fmaf(qx[q], p.x, p.w);   // p.w = -0.5|p|^2
            v = fmaf(qy[q], p.y, v);
            v = fmaf(qz[q], p.z, v);
            t2[q] = fmaxf(t2[q], fminf(v, t1[q]));  // uses old t1
            t1[q] = fmaxf(t1[q], v);
        }
    }

    float thr[QPW];
#pragma unroll
    for (int q = 0; q < QPW; q++) {
        unsigned k0 = ~ordf(t1[q]);
        unsigned k1 = ~ordf(t2[q]);
        bitonic64_u32(k0, k1, lane);
        unsigned s39 = __shfl_sync(FULL, k1, 7);   // slot 39 = 40th largest
        thr[q] = unordf(~s39);
    }

    // ---- pass 2: collect indices with v >= thr ----
    int cnt[QPW];
#pragma unroll
    for (int q = 0; q < QPW; q++) cnt[q] = 0;
    const unsigned lmlt = (1u << lane) - 1u;

#pragma unroll 4
    for (int it = 0; it < NPTS; it += 32) {
        float4 p = __ldg(bp + it + lane);
        float v[QPW];
        bool any = false;
#pragma unroll
        for (int q = 0; q < QPW; q++) {
            float vv = fmaf(qx[q], p.x, p.w);
            vv = fmaf(qy[q], p.y, vv);
            vv = fmaf(qz[q], p.z, vv);
            v[q] = vv;
            any |= (vv >= thr[q]);
        }
        if (__ballot_sync(FULL, any)) {
            int idx = it + lane;
#pragma unroll
            for (int q = 0; q < QPW; q++) {
                unsigned mq = __ballot_sync(FULL, v[q] >= thr[q]);
                if (mq) {
                    if (v[q] >= thr[q]) {
                        int pos = cnt[q] + __popc(mq & lmlt);
                        if (pos < CAP)
                            buf[q * CAP + pos] = (unsigned)idx;
                    }
                    cnt[q] += __popc(mq);
                }
            }
        }
    }

    // ---- epilogue: recompute w, sort, select top-40, gather ----
#pragma unroll 1
    for (int q = 0; q < QPW; q++) {
        unsigned* bq = buf + q * CAP;
        int c = min(cnt[q], CAP);
        const float ax = qx[q], ay = qy[q], az = qz[q];

        auto mkkey = [&](int slot) -> unsigned long long {
            if (slot >= c) return ~0ULL;
            unsigned idx = bq[slot];
            float4 p = __ldg(bp + idx);
            float v = fmaf(ax, p.x, p.w);
            v = fmaf(ay, p.y, v);
            v = fmaf(az, p.z, v);
            return (((unsigned long long)(~ordf(v))) << 13) | idx;
        };

        unsigned long long k0 = mkkey(lane);
        unsigned long long k1 = mkkey(32 + lane);
        bitonic64_u64(k0, k1, lane);
        for (int base = 64; base < c; base += 64) {
            unsigned long long s0 = mkkey(base + lane);
            unsigned long long s1 = mkkey(base + 32 + lane);
            bitonic64_u64(s0, s1, lane);
            merge64(k0, k1, s0, s1, lane);
        }
        float4* o = g_nb + (size_t)(q0 + q) * KMAX;
        o[lane] = __ldg(bp + (int)(k0 & 8191u));
        if (lane < 8) o[32 + lane] = __ldg(bp + (int)(k1 & 8191u));
    }
}

// ---------------------------------------------------------------------------
// Phase 2: edge conv + folded BN + LeakyReLU (after max; monotone) + max.
// 256 threads = 4 points x 64 channels; neighbors streamed from g_nb;
// output staged in smem and written as coalesced float4 (4 consecutive n).
// ---------------------------------------------------------------------------
__global__ void __launch_bounds__(64 * EPTS) edgeconv_kernel(
    const float* __restrict__ W,
    const float* __restrict__ gamma, const float* __restrict__ beta,
    const float* __restrict__ mean, const float* __restrict__ var,
    float* __restrict__ out)
{
    __shared__ float4 snb[EPTS][KMAX];
    __shared__ float  sres[3][EPTS][COUT];

    const int t = threadIdx.x;
    const int grp = t >> 6, o = t & 63;
    const int bn0 = blockIdx.x * EPTS;
    const int bn = bn0 + grp;
    const int b = bn >> 13;                     // all 4 points same batch

    if (o < KMAX) snb[grp][o] = g_nb[(size_t)bn * KMAX + o];
    const float4 c = g_pts[bn];
    __syncthreads();

    const float cx = c.x, cy = c.y, cz = c.z;

    float wd[3][3], basec[3];
#pragma unroll
    for (int s = 0; s < 3; s++) {
        const float* Ws = W + (s * COUT + o) * 6;
        float w0 = Ws[0], w1 = Ws[1], w2 = Ws[2];
        float w3 = Ws[3], w4 = Ws[4], w5 = Ws[5];
        int so = s * COUT + o;
        float inv  = gamma[so] * rsqrtf(var[so] + BN_EPS);
        float bias = beta[so] - mean[so] * inv;
        float bse = (w3 - w0) * cx;
        bse = fmaf(w4 - w1, cy, bse);
        bse = fmaf(w5 - w2, cz, bse);
        wd[s][0] = w0 * inv; wd[s][1] = w1 * inv; wd[s][2] = w2 * inv;
        basec[s] = fmaf(bse, inv, bias);
    }

    float m0 = -CUDART_INF_F, m1 = -CUDART_INF_F, m2 = -CUDART_INF_F;
#pragma unroll
    for (int j = 0; j < K0; j++) {
        float4 p = snb[grp][j];
        float t0 = fmaf(wd[0][0], p.x, basec[0]);
        t0 = fmaf(wd[0][1], p.y, t0); t0 = fmaf(wd[0][2], p.z, t0);
        m0 = fmaxf(m0, t0);
        float t1 = fmaf(wd[1][0], p.x, basec[1]);
        t1 = fmaf(wd[1][1], p.y, t1); t1 = fmaf(wd[1][2], p.z, t1);
        m1 = fmaxf(m1, t1);
        float t2 = fmaf(wd[2][0], p.x, basec[2]);
        t2 = fmaf(wd[2][1], p.y, t2); t2 = fmaf(wd[2][2], p.z, t2);
        m2 = fmaxf(m2, t2);
    }
#pragma unroll
    for (int j = K0; j < K1; j++) {
        float4 p = snb[grp][j];
        float t1 = fmaf(wd[1][0], p.x, basec[1]);
        t1 = fmaf(wd[1][1], p.y, t1); t1 = fmaf(wd[1][2], p.z, t1);
        m1 = fmaxf(m1, t1);
        float t2 = fmaf(wd[2][0], p.x, basec[2]);
        t2 = fmaf(wd[2][1], p.y, t2); t2 = fmaf(wd[2][2], p.z, t2);
        m2 = fmaxf(m2, t2);
    }
#pragma unroll
    for (int j = K1; j < KMAX; j++) {
        float4 p = snb[grp][j];
        float t2 = fmaf(wd[2][0], p.x, basec[2]);
        t2 = fmaf(wd[2][1], p.y, t2); t2 = fmaf(wd[2][2], p.z, t2);
        m2 = fmaxf(m2, t2);
    }

    m0 = fmaxf(m0, 0.2f * m0);
    m1 = fmaxf(m1, 0.2f * m1);
    m2 = fmaxf(m2, 0.2f * m2);

    sres[0][grp][o] = m0;
    sres[1][grp][o] = m1;
    sres[2][grp][o] = m2;
    __syncthreads();

    if (t < 192) {
        int s = t >> 6, oo = t & 63;
        float4 vv = make_float4(sres[s][0][oo], sres[s][1][oo],
                                sres[s][2][oo], sres[s][3][oo]);
        const int n0 = bn0 & (NPTS - 1);
        size_t basep = ((size_t)s * B * COUT + (size_t)b * COUT + oo) * NPTS + n0;
        *(float4*)(out + basep) = vv;
    }
}

extern "C" void kernel_launch(void* const* d_in, const int* in_sizes, int n_in,
                              void* d_out, int out_size) {
    const float* x     = (const float*)d_in[0];
    const float* W     = (const float*)d_in[1];
    const float* gamma = (const float*)d_in[2];
    const float* beta  = (const float*)d_in[3];
    const float* mean  = (const float*)d_in[4];
    const float* var   = (const float*)d_in[5];
    float* out = (float*)d_out;

    pack_kernel<<<(B * NPTS) / 256, 256>>>(x);
    topk_kernel<<<(B * NPTS) / (QPW * WPB), 32 * WPB>>>();
    edgeconv_kernel<<<(B * NPTS) / EPTS, 64 * EPTS>>>(W, gamma, beta, mean, var, out);
}

// round 11
// speedup vs baseline: 1.1842x; 1.1842x over previous
#include <cuda_runtime.h>
#include <math_constants.h>

#define B     4
#define CIN   3
#define NPTS  8192
#define COUT  64
#define KMAX  40
#define K0    10
#define K1    20
#define BN_EPS 1e-5f
#define FULL  0xFFFFFFFFu
#define WPB   8          // warps per block (topk)
#define QPW   4          // queries per warp
#define CAP   128        // candidate buffer capacity per query
#define EPTS  4          // points per block (edgeconv)

// packed points: (x, y, z, -0.5*||p||^2)
__device__ float4 g_pts[B * NPTS];
// gathered neighbor coords per (b,n): 40 float4, sorted by descending dist
__device__ float4 g_nb[(size_t)B * NPTS * KMAX];

// monotone float<->uint transforms (order-preserving over all finite floats)
__device__ __forceinline__ unsigned ordf(float f) {
    unsigned u = __float_as_uint(f);
    return u ^ (unsigned)(((int)u >> 31) | 0x80000000);
}
__device__ __forceinline__ float unordf(unsigned o) {
    unsigned u = (o & 0x80000000u) ? (o ^ 0x80000000u) : ~o;
    return __uint_as_float(u);
}

__device__ __forceinline__ unsigned long long u64mn(unsigned long long a, unsigned long long b) { return a < b ? a : b; }
__device__ __forceinline__ unsigned long long u64mx(unsigned long long a, unsigned long long b) { return a > b ? a : b; }
__device__ __forceinline__ unsigned u32mn(unsigned a, unsigned b) { return a < b ? a : b; }
__device__ __forceinline__ unsigned u32mx(unsigned a, unsigned b) { return a > b ? a : b; }

// ascending bitonic sort of 64 u32 keys, 2 per lane (slot lane, slot lane+32)
__device__ __forceinline__ void bitonic64_u32(unsigned &k0, unsigned &k1, int lane) {
#pragma unroll
    for (int k = 2; k <= 64; k <<= 1) {
#pragma unroll
        for (int s = 32; s > 0; s >>= 1) {
            if (s >= k) continue;
            if (s == 32) {
                unsigned lo = u32mn(k0, k1), hi = u32mx(k0, k1);
                k0 = lo; k1 = hi;
            } else {
                unsigned p0 = __shfl_xor_sync(FULL, k0, s);
                unsigned p1 = __shfl_xor_sync(FULL, k1, s);
                bool low = (lane & s) == 0;
                bool d0 = (lane & k) == 0;
                bool d1 = ((lane + 32) & k) == 0;
                k0 = (low == d0) ? u32mn(k0, p0) : u32mx(k0, p0);
                k1 = (low == d1) ? u32mn(k1, p1) : u32mx(k1, p1);
            }
        }
    }
}

// ascending bitonic sort of 64 u64 keys, 2 per lane
__device__ __forceinline__ void bitonic64_u64(unsigned long long &k0,
                                              unsigned long long &k1, int lane) {
#pragma unroll
    for (int k = 2; k <= 64; k <<= 1) {
#pragma unroll
        for (int s = 32; s > 0; s >>= 1) {
            if (s >= k) continue;
            if (s == 32) {
                unsigned long long lo = u64mn(k0, k1), hi = u64mx(k0, k1);
                k0 = lo; k1 = hi;
            } else {
                unsigned long long p0 = __shfl_xor_sync(FULL, k0, s);
                unsigned long long p1 = __shfl_xor_sync(FULL, k1, s);
                bool low = (lane & s) == 0;
                bool d0 = (lane & k) == 0;
                bool d1 = ((lane + 32) & k) == 0;
                k0 = (low == d0) ? u64mn(k0, p0) : u64mx(k0, p0);
                k1 = (low == d1) ? u64mn(k1, p1) : u64mx(k1, p1);
            }
        }
    }
}

// merge sorted-asc (k0,k1) with sorted-asc (s0,s1): keep smallest 64, sorted asc
__device__ __forceinline__ void merge64(unsigned long long &k0, unsigned long long &k1,
                                        unsigned long long s0, unsigned long long s1,
                                        int lane) {
    unsigned long long r0 = __shfl_sync(FULL, s1, 31 - lane);
    unsigned long long r1 = __shfl_sync(FULL, s0, 31 - lane);
    k0 = u64mn(k0, r0);
    k1 = u64mn(k1, r1);
    unsigned long long lo = u64mn(k0, k1), hi = u64mx(k0, k1);
    k0 = lo; k1 = hi;
#pragma unroll
    for (int s = 16; s > 0; s >>= 1) {
        unsigned long long p0 = __shfl_xor_sync(FULL, k0, s);
        unsigned long long p1 = __shfl_xor_sync(FULL, k1, s);
        bool low = (lane & s) == 0;
        k0 = low ? u64mn(k0, p0) : u64mx(k0, p0);
        k1 = low ? u64mn(k1, p1) : u64mx(k1, p1);
    }
}

// ---------------------------------------------------------------------------
// Phase 0: pack planar [B,3,N] into float4 (x,y,z, -0.5*|p|^2)
// ---------------------------------------------------------------------------
__global__ void pack_kernel(const float* __restrict__ x) {
    int i = blockIdx.x * blockDim.x + threadIdx.x;   // 0 .. B*NPTS-1
    int b = i >> 13;
    int m = i & (NPTS - 1);
    const float* xb = x + (size_t)b * CIN * NPTS;
    float px = xb[m];
    float py = xb[NPTS + m];
    float pz = xb[2 * NPTS + m];
    float t = px * px;
    t = fmaf(py, py, t);
    t = fmaf(pz, pz, t);
    g_pts[i] = make_float4(px, py, pz, -0.5f * t);
}

// ---------------------------------------------------------------------------
// Phase 1: two-pass exact top-40, 4 queries per warp, candidates via L1.
// Ranking uses w(p) = <q,p> - 0.5|p|^2, a strictly monotone per-query
// transform of -|q-p|^2: identical neighbor ordering.
// Pass 1: per-lane top-2 (branch-free) -> bitonic64 -> 40th of kept 64 =
//         threshold (40th of ANY 64-subset <= true 40th => conservative).
// Pass 2: accepting lanes append their INDEX to a per-query smem buffer via
//         atomicAdd on a per-(warp,query) counter — no ballots, no ordered
//         compaction. Buffer order is irrelevant: the epilogue sort on
//         (w desc, idx asc) keys fully determines the exact result.
// Epilogue: recompute w for survivors (identical expression => bit-equal),
//         sort keys (~ord(w)<<13 | idx) == lax.top_k order; gather to g_nb.
// ---------------------------------------------------------------------------
__global__ void __launch_bounds__(32 * WPB, 4) topk_kernel() {
    __shared__ unsigned bufall[WPB * QPW * CAP];   // 16 KB
    __shared__ int cntall[WPB * QPW];              // 128 B

    const int lane = threadIdx.x & 31;
    const int warp = threadIdx.x >> 5;
    const int q0 = (blockIdx.x * WPB + warp) * QPW;   // b*NPTS + n
    const int b = q0 >> 13;                           // block stays in one batch
    const float4* __restrict__ bp = g_pts + b * NPTS;
    unsigned* buf = bufall + (size_t)warp * QPW * CAP;
    int* cnt = cntall + warp * QPW;

    if (lane < QPW) cnt[lane] = 0;
    __syncwarp();

    float qx[QPW], qy[QPW], qz[QPW];
#pragma unroll
    for (int q = 0; q < QPW; q++) {
        float4 Q = __ldg(&g_pts[q0 + q]);
        qx[q] = Q.x; qy[q] = Q.y; qz[q] = Q.z;
    }

    // ---- pass 1: per-lane top-2 ----
    float t1[QPW], t2[QPW];
#pragma unroll
    for (int q = 0; q < QPW; q++) { t1[q] = -CUDART_INF_F; t2[q] = -CUDART_INF_F; }

#pragma unroll 4
    for (int it = 0; it < NPTS; it += 32) {
        float4 p = __ldg(bp + it + lane);
#pragma unroll
        for (int q = 0; q < QPW; q++) {
            float v = fmaf(qx[q], p.x, p.w);   // p.w = -0.5|p|^2
            v = fmaf(qy[q], p.y, v);
            v = fmaf(qz[q], p.z, v);
            t2[q] = fmaxf(t2[q], fminf(v, t1[q]));  // uses old t1
            t1[q] = fmaxf(t1[q], v);
        }
    }

    float thr[QPW];
#pragma unroll
    for (int q = 0; q < QPW; q++) {
        unsigned k0 = ~ordf(t1[q]);
        unsigned k1 = ~ordf(t2[q]);
        bitonic64_u32(k0, k1, lane);
        unsigned s39 = __shfl_sync(FULL, k1, 7);   // slot 39 = 40th largest
        thr[q] = unordf(~s39);
    }

    // ---- pass 2: append indices with v >= thr (unordered, atomic) ----
#pragma unroll 4
    for (int it = 0; it < NPTS; it += 32) {
        float4 p = __ldg(bp + it + lane);
        int idx = it + lane;
#pragma unroll
        for (int q = 0; q < QPW; q++) {
            float vv = fmaf(qx[q], p.x, p.w);
            vv = fmaf(qy[q], p.y, vv);
            vv = fmaf(qz[q], p.z, vv);
            if (vv >= thr[q]) {
                int pos = atomicAdd(&cnt[q], 1);
                if (pos < CAP) buf[q * CAP + pos] = (unsigned)idx;
            }
        }
    }
    __syncwarp();

    // ---- epilogue: recompute w, sort, select top-40, gather ----
#pragma unroll 1
    for (int q = 0; q < QPW; q++) {
        unsigned* bq = buf + q * CAP;
        int c = min(cnt[q], CAP);
        const float ax = qx[q], ay = qy[q], az = qz[q];

        auto mkkey = [&](int slot) -> unsigned long long {
            if (slot >= c) return ~0ULL;
            unsigned idx = bq[slot];
            float4 p = __ldg(bp + idx);
            float v = fmaf(ax, p.x, p.w);
            v = fmaf(ay, p.y, v);
            v = fmaf(az, p.z, v);
            return (((unsigned long long)(~ordf(v))) << 13) | idx;
        };

        unsigned long long k0 = mkkey(lane);
        unsigned long long k1 = mkkey(32 + lane);
        bitonic64_u64(k0, k1, lane);
        for (int base = 64; base < c; base += 64) {
            unsigned long long s0 = mkkey(base + lane);
            unsigned long long s1 = mkkey(base + 32 + lane);
            bitonic64_u64(s0, s1, lane);
            merge64(k0, k1, s0, s1, lane);
        }
        float4* o = g_nb + (size_t)(q0 + q) * KMAX;
        o[lane] = __ldg(bp + (int)(k0 & 8191u));
        if (lane < 8) o[32 + lane] = __ldg(bp + (int)(k1 & 8191u));
    }
}

// ---------------------------------------------------------------------------
// Phase 2: edge conv + folded BN + LeakyReLU (after max; monotone) + max.
// 256 threads = 4 points x 64 channels; neighbors streamed from g_nb;
// output staged in smem and written as coalesced float4 (4 consecutive n).
// ---------------------------------------------------------------------------
__global__ void __launch_bounds__(64 * EPTS) edgeconv_kernel(
    const float* __restrict__ W,
    const float* __restrict__ gamma, const float* __restrict__ beta,
    const float* __restrict__ mean, const float* __restrict__ var,
    float* __restrict__ out)
{
    __shared__ float4 snb[EPTS][KMAX];
    __shared__ float  sres[3][EPTS][COUT];

    const int t = threadIdx.x;
    const int grp = t >> 6, o = t & 63;
    const int bn0 = blockIdx.x * EPTS;
    const int bn = bn0 + grp;
    const int b = bn >> 13;                     // all 4 points same batch

    if (o < KMAX) snb[grp][o] = g_nb[(size_t)bn * KMAX + o];
    const float4 c = g_pts[bn];
    __syncthreads();

    const float cx = c.x, cy = c.y, cz = c.z;

    float wd[3][3], basec[3];
#pragma unroll
    for (int s = 0; s < 3; s++) {
        const float* Ws = W + (s * COUT + o) * 6;
        float w0 = Ws[0], w1 = Ws[1], w2 = Ws[2];
        float w3 = Ws[3], w4 = Ws[4], w5 = Ws[5];
        int so = s * COUT + o;
        float inv  = gamma[so] * rsqrtf(var[so] + BN_EPS);
        float bias = beta[so] - mean[so] * inv;
        float bse = (w3 - w0) * cx;
        bse = fmaf(w4 - w1, cy, bse);
        bse = fmaf(w5 - w2, cz, bse);
        wd[s][0] = w0 * inv; wd[s][1] = w1 * inv; wd[s][2] = w2 * inv;
        basec[s] = fmaf(bse, inv, bias);
    }

    float m0 = -CUDART_INF_F, m1 = -CUDART_INF_F, m2 = -CUDART_INF_F;
#pragma unroll
    for (int j = 0; j < K0; j++) {
        float4 p = snb[grp][j];
        float t0 = fmaf(wd[0][0], p.x, basec[0]);
        t0 = fmaf(wd[0][1], p.y, t0); t0 = fmaf(wd[0][2], p.z, t0);
        m0 = fmaxf(m0, t0);
        float t1 = fmaf(wd[1][0], p.x, basec[1]);
        t1 = fmaf(wd[1][1], p.y, t1); t1 = fmaf(wd[1][2], p.z, t1);
        m1 = fmaxf(m1, t1);
        float t2 = fmaf(wd[2][0], p.x, basec[2]);
        t2 = fmaf(wd[2][1], p.y, t2); t2 = fmaf(wd[2][2], p.z, t2);
        m2 = fmaxf(m2, t2);
    }
#pragma unroll
    for (int j = K0; j < K1; j++) {
        float4 p = snb[grp][j];
        float t1 = fmaf(wd[1][0], p.x, basec[1]);
        t1 = fmaf(wd[1][1], p.y, t1); t1 = fmaf(wd[1][2], p.z, t1);
        m1 = fmaxf(m1, t1);
        float t2 = fmaf(wd[2][0], p.x, basec[2]);
        t2 = fmaf(wd[2][1], p.y, t2); t2 = fmaf(wd[2][2], p.z, t2);
        m2 = fmaxf(m2, t2);
    }
#pragma unroll
    for (int j = K1; j < KMAX; j++) {
        float4 p = snb[grp][j];
        float t2 = fmaf(wd[2][0], p.x, basec[2]);
        t2 = fmaf(wd[2][1], p.y, t2); t2 = fmaf(wd[2][2], p.z, t2);
        m2 = fmaxf(m2, t2);
    }

    m0 = fmaxf(m0, 0.2f * m0);
    m1 = fmaxf(m1, 0.2f * m1);
    m2 = fmaxf(m2, 0.2f * m2);

    sres[0][grp][o] = m0;
    sres[1][grp][o] = m1;
    sres[2][grp][o] = m2;
    __syncthreads();

    if (t < 192) {
        int s = t >> 6, oo = t & 63;
        float4 vv = make_float4(sres[s][0][oo], sres[s][1][oo],
                                sres[s][2][oo], sres[s][3][oo]);
        const int n0 = bn0 & (NPTS - 1);
        size_t basep = ((size_t)s * B * COUT + (size_t)b * COUT + oo) * NPTS + n0;
        *(float4*)(out + basep) = vv;
    }
}

extern "C" void kernel_launch(void* const* d_in, const int* in_sizes, int n_in,
                              void* d_out, int out_size) {
    const float* x     = (const float*)d_in[0];
    const float* W     = (const float*)d_in[1];
    const float* gamma = (const float*)d_in[2];
    const float* beta  = (const float*)d_in[3];
    const float* mean  = (const float*)d_in[4];
    const float* var   = (const float*)d_in[5];
    float* out = (float*)d_out;

    pack_kernel<<<(B * NPTS) / 256, 256>>>(x);
    topk_kernel<<<(B * NPTS) / (QPW * WPB), 32 * WPB>>>();
    edgeconv_kernel<<<(B * NPTS) / EPTS, 64 * EPTS>>>(W, gamma, beta, mean, var, out);
}

// round 12
// speedup vs baseline: 1.2027x; 1.0156x over previous
#include <cuda_runtime.h>
#include <math_constants.h>

#define B     4
#define CIN   3
#define NPTS  8192
#define COUT  64
#define KMAX  40
#define K0    10
#define K1    20
#define BN_EPS 1e-5f
#define FULL  0xFFFFFFFFu
#define WPB   8          // warps per block (topk)
#define QPW   4          // queries per warp
#define CAP   160        // candidate buffer capacity per query (mean ~80, 8.6σ)
#define EPTS  4          // points per block (edgeconv)

// packed points: (x, y, z, -0.5*||p||^2)
__device__ float4 g_pts[B * NPTS];
// gathered neighbor coords per (b,n): 40 float4, sorted by descending dist
__device__ float4 g_nb[(size_t)B * NPTS * KMAX];

// monotone float<->uint transforms (order-preserving over all finite floats)
__device__ __forceinline__ unsigned ordf(float f) {
    unsigned u = __float_as_uint(f);
    return u ^ (unsigned)(((int)u >> 31) | 0x80000000);
}
__device__ __forceinline__ float unordf(unsigned o) {
    unsigned u = (o & 0x80000000u) ? (o ^ 0x80000000u) : ~o;
    return __uint_as_float(u);
}

__device__ __forceinline__ unsigned long long u64mn(unsigned long long a, unsigned long long b) { return a < b ? a : b; }
__device__ __forceinline__ unsigned long long u64mx(unsigned long long a, unsigned long long b) { return a > b ? a : b; }
__device__ __forceinline__ unsigned u32mn(unsigned a, unsigned b) { return a < b ? a : b; }
__device__ __forceinline__ unsigned u32mx(unsigned a, unsigned b) { return a > b ? a : b; }

// ascending bitonic sort of 64 u32 keys, 2 per lane (slot lane, slot lane+32)
__device__ __forceinline__ void bitonic64_u32(unsigned &k0, unsigned &k1, int lane) {
#pragma unroll
    for (int k = 2; k <= 64; k <<= 1) {
#pragma unroll
        for (int s = 32; s > 0; s >>= 1) {
            if (s >= k) continue;
            if (s == 32) {
                unsigned lo = u32mn(k0, k1), hi = u32mx(k0, k1);
                k0 = lo; k1 = hi;
            } else {
                unsigned p0 = __shfl_xor_sync(FULL, k0, s);
                unsigned p1 = __shfl_xor_sync(FULL, k1, s);
                bool low = (lane & s) == 0;
                bool d0 = (lane & k) == 0;
                bool d1 = ((lane + 32) & k) == 0;
                k0 = (low == d0) ? u32mn(k0, p0) : u32mx(k0, p0);
                k1 = (low == d1) ? u32mn(k1, p1) : u32mx(k1, p1);
            }
        }
    }
}

// ascending bitonic sort of 64 u64 keys, 2 per lane
__device__ __forceinline__ void bitonic64_u64(unsigned long long &k0,
                                              unsigned long long &k1, int lane) {
#pragma unroll
    for (int k = 2; k <= 64; k <<= 1) {
#pragma unroll
        for (int s = 32; s > 0; s >>= 1) {
            if (s >= k) continue;
            if (s == 32) {
                unsigned long long lo = u64mn(k0, k1), hi = u64mx(k0, k1);
                k0 = lo; k1 = hi;
            } else {
                unsigned long long p0 = __shfl_xor_sync(FULL, k0, s);
                unsigned long long p1 = __shfl_xor_sync(FULL, k1, s);
                bool low = (lane & s) == 0;
                bool d0 = (lane & k) == 0;
                bool d1 = ((lane + 32) & k) == 0;
                k0 = (low == d0) ? u64mn(k0, p0) : u64mx(k0, p0);
                k1 = (low == d1) ? u64mn(k1, p1) : u64mx(k1, p1);
            }
        }
    }
}

// merge sorted-asc (k0,k1) with sorted-asc (s0,s1): keep smallest 64, sorted asc
__device__ __forceinline__ void merge64(unsigned long long &k0, unsigned long long &k1,
                                        unsigned long long s0, unsigned long long s1,
                                        int lane) {
    unsigned long long r0 = __shfl_sync(FULL, s1, 31 - lane);
    unsigned long long r1 = __shfl_sync(FULL, s0, 31 - lane);
    k0 = u64mn(k0, r0);
    k1 = u64mn(k1, r1);
    unsigned long long lo = u64mn(k0, k1), hi = u64mx(k0, k1);
    k0 = lo; k1 = hi;
#pragma unroll
    for (int s = 16; s > 0; s >>= 1) {
        unsigned long long p0 = __shfl_xor_sync(FULL, k0, s);
        unsigned long long p1 = __shfl_xor_sync(FULL, k1, s);
        bool low = (lane & s) == 0;
        k0 = low ? u64mn(k0, p0) : u64mx(k0, p0);
        k1 = low ? u64mn(k1, p1) : u64mx(k1, p1);
    }
}

// ---------------------------------------------------------------------------
// Phase 0: pack planar [B,3,N] into float4 (x,y,z, -0.5*|p|^2)
// ---------------------------------------------------------------------------
__global__ void pack_kernel(const float* __restrict__ x) {
    int i = blockIdx.x * blockDim.x + threadIdx.x;   // 0 .. B*NPTS-1
    int b = i >> 13;
    int m = i & (NPTS - 1);
    const float* xb = x + (size_t)b * CIN * NPTS;
    float px = xb[m];
    float py = xb[NPTS + m];
    float pz = xb[2 * NPTS + m];
    float t = px * px;
    t = fmaf(py, py, t);
    t = fmaf(pz, pz, t);
    g_pts[i] = make_float4(px, py, pz, -0.5f * t);
}

// ---------------------------------------------------------------------------
// Phase 1: two-pass exact top-40, 4 queries per warp, candidates via L1.
// Ranking uses w(p) = <q,p> - 0.5|p|^2, a strictly monotone per-query
// transform of -|q-p|^2: identical neighbor ordering.
// Pass 1 (HALF-SAMPLE): per-lane top-2 over the even 32-blocks (4096 pts)
//         -> bitonic64 -> 40th of the kept 64 sample elements = threshold.
//         40th-largest of ANY stream subset <= true 40th => conservative;
//         exactness lives entirely in pass 2 + sort.
// Pass 2: accepting lanes append their INDEX to a per-query smem buffer via
//         atomicAdd on a per-(warp,query) counter — no ballots. Buffer order
//         irrelevant: epilogue sort fully determines the exact result.
//         E[count] ~ 80, CAP=160 (~8.6σ).
// Epilogue: recompute w for survivors (identical expression => bit-equal),
//         sort keys (~ord(w)<<13 | idx) == (w desc, idx asc) == lax.top_k
//         order; gather neighbor float4s to g_nb.
// ---------------------------------------------------------------------------
__global__ void __launch_bounds__(32 * WPB, 4) topk_kernel() {
    __shared__ unsigned bufall[WPB * QPW * CAP];   // 20 KB
    __shared__ int cntall[WPB * QPW];              // 128 B

    const int lane = threadIdx.x & 31;
    const int warp = threadIdx.x >> 5;
    const int q0 = (blockIdx.x * WPB + warp) * QPW;   // b*NPTS + n
    const int b = q0 >> 13;                           // block stays in one batch
    const float4* __restrict__ bp = g_pts + b * NPTS;
    unsigned* buf = bufall + (size_t)warp * QPW * CAP;
    int* cnt = cntall + warp * QPW;

    if (lane < QPW) cnt[lane] = 0;
    __syncwarp();

    float qx[QPW], qy[QPW], qz[QPW];
#pragma unroll
    for (int q = 0; q < QPW; q++) {
        float4 Q = __ldg(&g_pts[q0 + q]);
        qx[q] = Q.x; qy[q] = Q.y; qz[q] = Q.z;
    }

    // ---- pass 1: per-lane top-2 over half-sample (even 32-blocks) ----
    float t1[QPW], t2[QPW];
#pragma unroll
    for (int q = 0; q < QPW; q++) { t1[q] = -CUDART_INF_F; t2[q] = -CUDART_INF_F; }

#pragma unroll 4
    for (int it = 0; it < NPTS; it += 64) {
        float4 p = __ldg(bp + it + lane);
#pragma unroll
        for (int q = 0; q < QPW; q++) {
            float v = fmaf(qx[q], p.x, p.w);   // p.w = -0.5|p|^2
            v = fmaf(qy[q], p.y, v);
            v = fmaf(qz[q], p.z, v);
            t2[q] = fmaxf(t2[q], fminf(v, t1[q]));  // uses old t1
            t1[q] = fmaxf(t1[q], v);
        }
    }

    float thr[QPW];
#pragma unroll
    for (int q = 0; q < QPW; q++) {
        unsigned k0 = ~ordf(t1[q]);
        unsigned k1 = ~ordf(t2[q]);
        bitonic64_u32(k0, k1, lane);
        unsigned s39 = __shfl_sync(FULL, k1, 7);   // slot 39 = 40th largest
        thr[q] = unordf(~s39);
    }

    // ---- pass 2: append indices with v >= thr (unordered, atomic) ----
#pragma unroll 4
    for (int it = 0; it < NPTS; it += 32) {
        float4 p = __ldg(bp + it + lane);
        int idx = it + lane;
#pragma unroll
        for (int q = 0; q < QPW; q++) {
            float vv = fmaf(qx[q], p.x, p.w);
            vv = fmaf(qy[q], p.y, vv);
            vv = fmaf(qz[q], p.z, vv);
            if (vv >= thr[q]) {
                int pos = atomicAdd(&cnt[q], 1);
                if (pos < CAP) buf[q * CAP + pos] = (unsigned)idx;
            }
        }
    }
    __syncwarp();

    // ---- epilogue: recompute w, sort, select top-40, gather ----
#pragma unroll 1
    for (int q = 0; q < QPW; q++) {
        unsigned* bq = buf + q * CAP;
        int c = min(cnt[q], CAP);
        const float ax = qx[q], ay = qy[q], az = qz[q];

        auto mkkey = [&](int slot) -> unsigned long long {
            if (slot >= c) return ~0ULL;
            unsigned idx = bq[slot];
            float4 p = __ldg(bp + idx);
            float v = fmaf(ax, p.x, p.w);
            v = fmaf(ay, p.y, v);
            v = fmaf(az, p.z, v);
            return (((unsigned long long)(~ordf(v))) << 13) | idx;
        };

        unsigned long long k0 = mkkey(lane);
        unsigned long long k1 = mkkey(32 + lane);
        bitonic64_u64(k0, k1, lane);
        for (int base = 64; base < c; base += 64) {
            unsigned long long s0 = mkkey(base + lane);
            unsigned long long s1 = mkkey(base + 32 + lane);
            bitonic64_u64(s0, s1, lane);
            merge64(k0, k1, s0, s1, lane);
        }
        float4* o = g_nb + (size_t)(q0 + q) * KMAX;
        o[lane] = __ldg(bp + (int)(k0 & 8191u));
        if (lane < 8) o[32 + lane] = __ldg(bp + (int)(k1 & 8191u));
    }
}

// ---------------------------------------------------------------------------
// Phase 2: edge conv + folded BN + LeakyReLU (after max; monotone) + max.
// 256 threads = 4 points x 64 channels; neighbors streamed from g_nb;
// output staged in smem and written as coalesced float4 (4 consecutive n).
// ---------------------------------------------------------------------------
__global__ void __launch_bounds__(64 * EPTS) edgeconv_kernel(
    const float* __restrict__ W,
    const float* __restrict__ gamma, const float* __restrict__ beta,
    const float* __restrict__ mean, const float* __restrict__ var,
    float* __restrict__ out)
{
    __shared__ float4 snb[EPTS][KMAX];
    __shared__ float  sres[3][EPTS][COUT];

    const int t = threadIdx.x;
    const int grp = t >> 6, o = t & 63;
    const int bn0 = blockIdx.x * EPTS;
    const int bn = bn0 + grp;
    const int b = bn >> 13;                     // all 4 points same batch

    if (o < KMAX) snb[grp][o] = g_nb[(size_t)bn * KMAX + o];
    const float4 c = g_pts[bn];
    __syncthreads();

    const float cx = c.x, cy = c.y, cz = c.z;

    float wd[3][3], basec[3];
#pragma unroll
    for (int s = 0; s < 3; s++) {
        const float* Ws = W + (s * COUT + o) * 6;
        float w0 = Ws[0], w1 = Ws[1], w2 = Ws[2];
        float w3 = Ws[3], w4 = Ws[4], w5 = Ws[5];
        int so = s * COUT + o;
        float inv  = gamma[so] * rsqrtf(var[so] + BN_EPS);
        float bias = beta[so] - mean[so] * inv;
        float bse = (w3 - w0) * cx;
        bse = fmaf(w4 - w1, cy, bse);
        bse = fmaf(w5 - w2, cz, bse);
        wd[s][0] = w0 * inv; wd[s][1] = w1 * inv; wd[s][2] = w2 * inv;
        basec[s] = fmaf(bse, inv, bias);
    }

    float m0 = -CUDART_INF_F, m1 = -CUDART_INF_F, m2 = -CUDART_INF_F;
#pragma unroll
    for (int j = 0; j < K0; j++) {
        float4 p = snb[grp][j];
        float t0 = fmaf(wd[0][0], p.x, basec[0]);
        t0 = fmaf(wd[0][1], p.y, t0); t0 = fmaf(wd[0][2], p.z, t0);
        m0 = fmaxf(m0, t0);
        float t1 = fmaf(wd[1][0], p.x, basec[1]);
        t1 = fmaf(wd[1][1], p.y, t1); t1 = fmaf(wd[1][2], p.z, t1);
        m1 = fmaxf(m1, t1);
        float t2 = fmaf(wd[2][0], p.x, basec[2]);
        t2 = fmaf(wd[2][1], p.y, t2); t2 = fmaf(wd[2][2], p.z, t2);
        m2 = fmaxf(m2, t2);
    }
#pragma unroll
    for (int j = K0; j < K1; j++) {
        float4 p = snb[grp][j];
        float t1 = fmaf(wd[1][0], p.x, basec[1]);
        t1 = fmaf(wd[1][1], p.y, t1); t1 = fmaf(wd[1][2], p.z, t1);
        m1 = fmaxf(m1, t1);
        float t2 = fmaf(wd[2][0], p.x, basec[2]);
        t2 = fmaf(wd[2][1], p.y, t2); t2 = fmaf(wd[2][2], p.z, t2);
        m2 = fmaxf(m2, t2);
    }
#pragma unroll
    for (int j = K1; j < KMAX; j++) {
        float4 p = snb[grp][j];
        float t2 = fmaf(wd[2][0], p.x, basec[2]);
        t2 = fmaf(wd[2][1], p.y, t2); t2 = fmaf(wd[2][2], p.z, t2);
        m2 = fmaxf(m2, t2);
    }

    m0 = fmaxf(m0, 0.2f * m0);
    m1 = fmaxf(m1, 0.2f * m1);
    m2 = fmaxf(m2, 0.2f * m2);

    sres[0][grp][o] = m0;
    sres[1][grp][o] = m1;
    sres[2][grp][o] = m2;
    __syncthreads();

    if (t < 192) {
        int s = t >> 6, oo = t & 63;
        float4 vv = make_float4(sres[s][0][oo], sres[s][1][oo],
                                sres[s][2][oo], sres[s][3][oo]);
        const int n0 = bn0 & (NPTS - 1);
        size_t basep = ((size_t)s * B * COUT + (size_t)b * COUT + oo) * NPTS + n0;
        *(float4*)(out + basep) = vv;
    }
}

extern "C" void kernel_launch(void* const* d_in, const int* in_sizes, int n_in,
                              void* d_out, int out_size) {
    const float* x     = (const float*)d_in[0];
    const float* W     = (const float*)d_in[1];
    const float* gamma = (const float*)d_in[2];
    const float* beta  = (const float*)d_in[3];
    const float* mean  = (const float*)d_in[4];
    const float* var   = (const float*)d_in[5];
    float* out = (float*)d_out;

    pack_kernel<<<(B * NPTS) / 256, 256>>>(x);
    topk_kernel<<<(B * NPTS) / (QPW * WPB), 32 * WPB>>>();
    edgeconv_kernel<<<(B * NPTS) / EPTS, 64 * EPTS>>>(W, gamma, beta, mean, var, out);
}